// round 2
// baseline (speedup 1.0000x reference)
#include <cuda_runtime.h>
#include <cuda_bf16.h>

// Problem constants (dataset-fixed)
#define D 128
#define BATCH 2
#define MAXN 50000
#define MAXBN (BATCH * MAXN)
#define LN_EPS 1e-5f

// Scratch: message matrix m = h @ W_msg^T, and aggregation buffer.
// MUST be 16B-aligned: accessed via float4 / red.global.add.v4.f32.
__device__ __align__(16) float g_m[MAXBN * D];    // 51.2 MB
__device__ __align__(16) float g_agg[MAXBN * D];  // 51.2 MB

// ---------------------------------------------------------------------------
// Kernel 0: zero the aggregation buffer (float4 stores, grid-stride)
// ---------------------------------------------------------------------------
__global__ void zero_agg_kernel(int total_f4) {
    int i = blockIdx.x * blockDim.x + threadIdx.x;
    int stride = gridDim.x * blockDim.x;
    float4 z = make_float4(0.f, 0.f, 0.f, 0.f);
    float4* p = reinterpret_cast<float4*>(g_agg);
    for (; i < total_f4; i += stride) p[i] = z;
}

// ---------------------------------------------------------------------------
// Kernel 1: m[row, f] = sum_k h[row, k] * W_msg[f, k]   (row over B*N)
// Tile: 64 rows x 128 outs, 256 threads, each thread 8x4 accumulators.
// smem: WT[k][f] (128x132 padded) + hT[k][n] (128x68 padded)
// ---------------------------------------------------------------------------
#define WT_STRIDE 132
#define XT_STRIDE 68

__global__ __launch_bounds__(256) void gemm_msg_kernel(
    const float* __restrict__ h, const float* __restrict__ W, int BN)
{
    extern __shared__ float sm[];
    float* WT = sm;                    // 128*132 floats
    float* hT = sm + 128 * WT_STRIDE;  // 128*68 floats

    int tid = threadIdx.x;
    int row0 = blockIdx.x * 64;

    // Load W_msg transposed: WT[k*132 + f] = W[f*128 + k]
    #pragma unroll 4
    for (int i = tid; i < D * D; i += 256) {
        int f = i >> 7, k = i & 127;
        WT[k * WT_STRIDE + f] = W[i];
    }
    // Load h tile transposed: hT[k*68 + n] = h[(row0+n)*128 + k]
    #pragma unroll 4
    for (int i = tid; i < 64 * D; i += 256) {
        int n = i >> 7, k = i & 127;
        int row = row0 + n;
        hT[k * XT_STRIDE + n] = (row < BN) ? h[row * D + k] : 0.f;
    }
    __syncthreads();

    int lane = tid & 31, trow = tid >> 5;
    int f0 = lane * 4, n0 = trow * 8;

    float acc[8][4];
    #pragma unroll
    for (int j = 0; j < 8; j++)
        #pragma unroll
        for (int c = 0; c < 4; c++) acc[j][c] = 0.f;

    #pragma unroll 4
    for (int k = 0; k < D; k++) {
        float4 b4 = *(const float4*)&WT[k * WT_STRIDE + f0];
        float4 a0 = *(const float4*)&hT[k * XT_STRIDE + n0];
        float4 a1 = *(const float4*)&hT[k * XT_STRIDE + n0 + 4];
        float a[8] = {a0.x, a0.y, a0.z, a0.w, a1.x, a1.y, a1.z, a1.w};
        #pragma unroll
        for (int j = 0; j < 8; j++) {
            acc[j][0] += a[j] * b4.x;
            acc[j][1] += a[j] * b4.y;
            acc[j][2] += a[j] * b4.z;
            acc[j][3] += a[j] * b4.w;
        }
    }

    #pragma unroll
    for (int j = 0; j < 8; j++) {
        int row = row0 + n0 + j;
        if (row < BN) {
            float4 o = make_float4(acc[j][0], acc[j][1], acc[j][2], acc[j][3]);
            *(float4*)&g_m[row * D + f0] = o;
        }
    }
}

// ---------------------------------------------------------------------------
// Kernel 2: edge scatter.  One warp per edge, both batches.
//   agg[b, tgt, :] += m[b, src, :] * rel_emb[rel, :]
// via red.global.add.v4.f32
// ---------------------------------------------------------------------------
__device__ __forceinline__ void red_add_v4(float* addr, float4 v) {
    asm volatile("red.global.add.v4.f32 [%0], {%1, %2, %3, %4};"
                 :: "l"(addr), "f"(v.x), "f"(v.y), "f"(v.z), "f"(v.w)
                 : "memory");
}

__global__ __launch_bounds__(256) void edge_scatter_kernel(
    const float* __restrict__ rel_emb,
    const int* __restrict__ src, const int* __restrict__ tgt,
    const int* __restrict__ rel, int E, int N)
{
    int w = (blockIdx.x * blockDim.x + threadIdx.x) >> 5;
    int lane = threadIdx.x & 31;
    if (w >= E) return;

    int s = __ldg(&src[w]);
    int t = __ldg(&tgt[w]);
    int r = __ldg(&rel[w]);

    float4 rv = *(const float4*)&rel_emb[r * D + lane * 4];

    #pragma unroll
    for (int b = 0; b < BATCH; b++) {
        const float4 mv = *(const float4*)&g_m[(b * N + s) * D + lane * 4];
        float4 p;
        p.x = mv.x * rv.x; p.y = mv.y * rv.y;
        p.z = mv.z * rv.z; p.w = mv.w * rv.w;
        red_add_v4(&g_agg[(b * N + t) * D + lane * 4], p);
    }
}

// ---------------------------------------------------------------------------
// Kernel 3: fused update GEMM + relu + residual + layernorm.
//   upd[row,d] = relu( sum_{k<128} h[row,k]*Wu[d,k]
//                    + sum_{k<128} agg[row,k]*Wu[d,128+k] + b_upd[d] )
//   out = LN(h + upd) * ln_scale + ln_bias
// Tile: 64 rows, 256 threads. smem: WuT (256x132) + x-tile (128x68),
// x-tile reused: h-phase then agg-phase.
// ---------------------------------------------------------------------------
__global__ __launch_bounds__(256) void gemm_upd_kernel(
    const float* __restrict__ h, const float* __restrict__ Wu,
    const float* __restrict__ b_upd, const float* __restrict__ ln_s,
    const float* __restrict__ ln_b, float* __restrict__ out, int BN)
{
    extern __shared__ float sm[];
    float* WT = sm;                        // 256*132 floats
    float* xT = sm + 256 * WT_STRIDE;      // 128*68 floats

    int tid = threadIdx.x;
    int row0 = blockIdx.x * 64;

    // Load W_upd transposed: WT[k*132 + d] = Wu[d*256 + k], k in [0,256)
    #pragma unroll 4
    for (int i = tid; i < D * 2 * D; i += 256) {
        int d = i >> 8, k = i & 255;
        WT[k * WT_STRIDE + d] = Wu[i];
    }
    // Phase A x-tile: h
    #pragma unroll 4
    for (int i = tid; i < 64 * D; i += 256) {
        int n = i >> 7, k = i & 127;
        int row = row0 + n;
        xT[k * XT_STRIDE + n] = (row < BN) ? h[row * D + k] : 0.f;
    }
    __syncthreads();

    int lane = tid & 31, trow = tid >> 5;
    int f0 = lane * 4, n0 = trow * 8;

    float acc[8][4];
    #pragma unroll
    for (int j = 0; j < 8; j++)
        #pragma unroll
        for (int c = 0; c < 4; c++) acc[j][c] = 0.f;

    // Phase A: k = 0..127 against h
    #pragma unroll 4
    for (int k = 0; k < D; k++) {
        float4 b4 = *(const float4*)&WT[k * WT_STRIDE + f0];
        float4 a0 = *(const float4*)&xT[k * XT_STRIDE + n0];
        float4 a1 = *(const float4*)&xT[k * XT_STRIDE + n0 + 4];
        float a[8] = {a0.x, a0.y, a0.z, a0.w, a1.x, a1.y, a1.z, a1.w};
        #pragma unroll
        for (int j = 0; j < 8; j++) {
            acc[j][0] += a[j] * b4.x;
            acc[j][1] += a[j] * b4.y;
            acc[j][2] += a[j] * b4.z;
            acc[j][3] += a[j] * b4.w;
        }
    }
    __syncthreads();

    // Phase B x-tile: agg
    #pragma unroll 4
    for (int i = tid; i < 64 * D; i += 256) {
        int n = i >> 7, k = i & 127;
        int row = row0 + n;
        xT[k * XT_STRIDE + n] = (row < BN) ? g_agg[row * D + k] : 0.f;
    }
    __syncthreads();

    // Phase B: k = 128..255 against agg
    #pragma unroll 4
    for (int k = 0; k < D; k++) {
        float4 b4 = *(const float4*)&WT[(D + k) * WT_STRIDE + f0];
        float4 a0 = *(const float4*)&xT[k * XT_STRIDE + n0];
        float4 a1 = *(const float4*)&xT[k * XT_STRIDE + n0 + 4];
        float a[8] = {a0.x, a0.y, a0.z, a0.w, a1.x, a1.y, a1.z, a1.w};
        #pragma unroll
        for (int j = 0; j < 8; j++) {
            acc[j][0] += a[j] * b4.x;
            acc[j][1] += a[j] * b4.y;
            acc[j][2] += a[j] * b4.z;
            acc[j][3] += a[j] * b4.w;
        }
    }

    // Epilogue: bias, relu, residual, layernorm (warp owns full rows)
    float4 bu  = *(const float4*)&b_upd[f0];
    float4 s4  = *(const float4*)&ln_s[f0];
    float4 bb4 = *(const float4*)&ln_b[f0];

    #pragma unroll
    for (int j = 0; j < 8; j++) {
        int row = row0 + n0 + j;           // uniform across warp
        if (row >= BN) continue;
        float4 hr = *(const float4*)&h[row * D + f0];
        float4 v;
        v.x = fmaxf(acc[j][0] + bu.x, 0.f) + hr.x;
        v.y = fmaxf(acc[j][1] + bu.y, 0.f) + hr.y;
        v.z = fmaxf(acc[j][2] + bu.z, 0.f) + hr.z;
        v.w = fmaxf(acc[j][3] + bu.w, 0.f) + hr.w;

        float sum = v.x + v.y + v.z + v.w;
        float ssq = v.x * v.x + v.y * v.y + v.z * v.z + v.w * v.w;
        #pragma unroll
        for (int o = 16; o > 0; o >>= 1) {
            sum += __shfl_xor_sync(0xFFFFFFFFu, sum, o);
            ssq += __shfl_xor_sync(0xFFFFFFFFu, ssq, o);
        }
        float mean = sum * (1.f / (float)D);
        float var  = ssq * (1.f / (float)D) - mean * mean;
        float rstd = rsqrtf(var + LN_EPS);

        float4 o4;
        o4.x = (v.x - mean) * rstd * s4.x + bb4.x;
        o4.y = (v.y - mean) * rstd * s4.y + bb4.y;
        o4.z = (v.z - mean) * rstd * s4.z + bb4.z;
        o4.w = (v.w - mean) * rstd * s4.w + bb4.w;
        *(float4*)&out[row * D + f0] = o4;
    }
}

// ---------------------------------------------------------------------------
// Launcher
// Input order (metadata.txt / setup_inputs):
//  0 h [B*N*D] f32, 1 W_msg [D*D], 2 rel_emb [R*D], 3 W_upd [D*2D],
//  4 b_upd [D], 5 ln_scale [D], 6 ln_bias [D],
//  7 edge_src [E] i32, 8 edge_tgt [E] i32, 9 edge_rel [E] i32, 10 nE scalar
// ---------------------------------------------------------------------------
extern "C" void kernel_launch(void* const* d_in, const int* in_sizes, int n_in,
                              void* d_out, int out_size)
{
    const float* h       = (const float*)d_in[0];
    const float* W_msg   = (const float*)d_in[1];
    const float* rel_emb = (const float*)d_in[2];
    const float* W_upd   = (const float*)d_in[3];
    const float* b_upd   = (const float*)d_in[4];
    const float* ln_s    = (const float*)d_in[5];
    const float* ln_b    = (const float*)d_in[6];
    const int*   e_src   = (const int*)d_in[7];
    const int*   e_tgt   = (const int*)d_in[8];
    const int*   e_rel   = (const int*)d_in[9];
    float* out = (float*)d_out;

    int BN = in_sizes[0] / D;      // B*N = 100000
    int N  = BN / BATCH;           // 50000
    int E  = in_sizes[7];          // 800000

    // Dynamic smem limits (>48KB). Idempotent non-stream API; legal under
    // graph capture.
    const size_t SMEM_MSG = (128 * WT_STRIDE + 128 * XT_STRIDE) * sizeof(float); // ~100 KB
    const size_t SMEM_UPD = (256 * WT_STRIDE + 128 * XT_STRIDE) * sizeof(float); // ~166 KB
    (void)cudaFuncSetAttribute(gemm_msg_kernel,
                               cudaFuncAttributeMaxDynamicSharedMemorySize, (int)SMEM_MSG);
    (void)cudaFuncSetAttribute(gemm_upd_kernel,
                               cudaFuncAttributeMaxDynamicSharedMemorySize, (int)SMEM_UPD);

    // 0) zero agg
    {
        int total_f4 = BN * D / 4;
        zero_agg_kernel<<<592, 256>>>(total_f4);
    }
    // 1) m = h @ W_msg^T
    {
        int blocks = (BN + 63) / 64;
        gemm_msg_kernel<<<blocks, 256, SMEM_MSG>>>(h, W_msg, BN);
    }
    // 2) edge scatter (one warp per edge)
    {
        int blocks = (E + 7) / 8;
        edge_scatter_kernel<<<blocks, 256>>>(rel_emb, e_src, e_tgt, e_rel, E, N);
    }
    // 3) fused update + LN
    {
        int blocks = (BN + 63) / 64;
        gemm_upd_kernel<<<blocks, 256, SMEM_UPD>>>(h, W_upd, b_upd, ln_s, ln_b, out, BN);
    }
}

// round 4
// speedup vs baseline: 1.4005x; 1.4005x over previous
#include <cuda_runtime.h>
#include <cuda_bf16.h>

// Problem constants (dataset-fixed)
#define D 128
#define BATCH 2
#define MAXN 50000
#define MAXBN (BATCH * MAXN)
#define LN_EPS 1e-5f

// Scratch buffers (16B-aligned: float4 / red.v4 / ulonglong2 access)
__device__ __align__(16) float g_m[MAXBN * D];    // h @ W_msg^T
__device__ __align__(16) float g_agg[MAXBN * D];  // scatter accumulator
__device__ __align__(16) float g_WmT[D * D];      // W_msg transposed [k][f]
__device__ __align__(16) float g_WuT[2 * D * D];  // W_upd transposed [k][d]

// ---- packed fp32x2 helpers (sm_100+) --------------------------------------
#define FMA2(d, a, b) \
    asm("fma.rn.f32x2 %0, %1, %2, %0;" : "+l"(d) : "l"(a), "l"(b))
#define SPLAT2(out, f) \
    asm("mov.b64 %0, {%1, %1};" : "=l"(out) : "r"(__float_as_uint(f)))
#define UNPACK2(lo, hi, v) \
    asm("mov.b64 {%0, %1}, %2;" : "=f"(lo), "=f"(hi) : "l"(v))

// smem geometry
#define XS_STRIDE 68   // 68*4 = 272 B, multiple of 16 -> aligned LDS.128 rows
#define WS_STRIDE 132  // 132*4 = 528 B, multiple of 16
#define KC 32          // K-chunk of W streamed through smem
// smem bytes: 128*68*4 + 32*132*4 = 34816 + 16896 = 51712
#define SMEM_GEMM ((128 * XS_STRIDE + KC * WS_STRIDE) * sizeof(float))

// ---------------------------------------------------------------------------
// Kernel T: transpose weights once per launch (reads coalesced)
// ---------------------------------------------------------------------------
__global__ void transpose_w_kernel(const float* __restrict__ Wm,
                                   const float* __restrict__ Wu) {
    int i = blockIdx.x * blockDim.x + threadIdx.x;   // grid covers 32768
    if (i < D * D) {                                  // Wm: [f][k] -> [k][f]
        int f = i >> 7, k = i & 127;
        g_WmT[k * D + f] = Wm[i];
    }
    if (i < 2 * D * D) {                              // Wu: [d][2D] -> [k][d]
        int d = i >> 8, k = i & 255;
        g_WuT[k * D + d] = Wu[i];
    }
}

// ---------------------------------------------------------------------------
// Kernel 0: zero the aggregation buffer
// ---------------------------------------------------------------------------
__global__ void zero_agg_kernel(int total_f4) {
    int i = blockIdx.x * blockDim.x + threadIdx.x;
    int stride = gridDim.x * blockDim.x;
    float4 z = make_float4(0.f, 0.f, 0.f, 0.f);
    float4* p = reinterpret_cast<float4*>(g_agg);
    for (; i < total_f4; i += stride) p[i] = z;
}

// ---------------------------------------------------------------------------
// Shared GEMM helpers
// x tile load: xs[k][n] (transposed), rows row0..row0+63, coalesced gmem read
// ---------------------------------------------------------------------------
__device__ __forceinline__ void load_xtile(float* xs, const float* __restrict__ X,
                                           int row0, int BN, int tid) {
    #pragma unroll 2
    for (int i = tid; i < 64 * 32; i += 256) {        // 64 rows x 32 float4
        int n = i >> 5, k4 = i & 31;
        int row = row0 + n;
        float4 v = make_float4(0.f, 0.f, 0.f, 0.f);
        if (row < BN) v = *(const float4*)&X[row * D + k4 * 4];
        xs[(k4 * 4 + 0) * XS_STRIDE + n] = v.x;
        xs[(k4 * 4 + 1) * XS_STRIDE + n] = v.y;
        xs[(k4 * 4 + 2) * XS_STRIDE + n] = v.z;
        xs[(k4 * 4 + 3) * XS_STRIDE + n] = v.w;
    }
}

__device__ __forceinline__ void load_wchunk(float* ws, const float* __restrict__ Wt,
                                            int tid) {
    #pragma unroll 2
    for (int i = tid; i < KC * 32; i += 256) {        // KC rows x 32 float4
        int kk = i >> 5, d4 = i & 31;
        float4 v = *(const float4*)&Wt[kk * D + d4 * 4];
        *(float4*)&ws[kk * WS_STRIDE + d4 * 4] = v;
    }
}

// inner product over one KC chunk: acc[4 row-pairs][4 cols] packed f32x2
__device__ __forceinline__ void mma_chunk(unsigned long long acc[4][4],
                                          const float* xs, const float* ws,
                                          int kbase, int n0, int d0) {
    #pragma unroll 4
    for (int kk = 0; kk < KC; kk++) {
        float4 b4 = *(const float4*)&ws[kk * WS_STRIDE + d0];
        unsigned long long bp0, bp1, bp2, bp3;
        SPLAT2(bp0, b4.x); SPLAT2(bp1, b4.y);
        SPLAT2(bp2, b4.z); SPLAT2(bp3, b4.w);
        const ulonglong2* ap =
            (const ulonglong2*)&xs[(kbase + kk) * XS_STRIDE + n0];
        ulonglong2 A0 = ap[0];   // row pairs (n0,n0+1),(n0+2,n0+3)
        ulonglong2 A1 = ap[1];   // row pairs (n0+4,n0+5),(n0+6,n0+7)
        FMA2(acc[0][0], A0.x, bp0); FMA2(acc[0][1], A0.x, bp1);
        FMA2(acc[0][2], A0.x, bp2); FMA2(acc[0][3], A0.x, bp3);
        FMA2(acc[1][0], A0.y, bp0); FMA2(acc[1][1], A0.y, bp1);
        FMA2(acc[1][2], A0.y, bp2); FMA2(acc[1][3], A0.y, bp3);
        FMA2(acc[2][0], A1.x, bp0); FMA2(acc[2][1], A1.x, bp1);
        FMA2(acc[2][2], A1.x, bp2); FMA2(acc[2][3], A1.x, bp3);
        FMA2(acc[3][0], A1.y, bp0); FMA2(acc[3][1], A1.y, bp1);
        FMA2(acc[3][2], A1.y, bp2); FMA2(acc[3][3], A1.y, bp3);
    }
}

// ---------------------------------------------------------------------------
// Kernel 1: m = h @ W_msg^T   (64-row x 128-col tile, chunked W)
// ---------------------------------------------------------------------------
__global__ __launch_bounds__(256, 3) void gemm_msg_kernel(
    const float* __restrict__ h, int BN)
{
    extern __shared__ float sm[];
    float* xs = sm;                    // 128 x 68
    float* ws = sm + 128 * XS_STRIDE;  // KC x 132

    int tid = threadIdx.x;
    int row0 = blockIdx.x * 64;
    int lane = tid & 31, w = tid >> 5;
    int d0 = lane * 4, n0 = w * 8;

    unsigned long long acc[4][4];
    #pragma unroll
    for (int p = 0; p < 4; p++)
        #pragma unroll
        for (int c = 0; c < 4; c++) acc[p][c] = 0ull;

    load_xtile(xs, h, row0, BN, tid);

    #pragma unroll 1
    for (int c0 = 0; c0 < D / KC; c0++) {
        __syncthreads();
        load_wchunk(ws, g_WmT + c0 * KC * D, tid);
        __syncthreads();
        mma_chunk(acc, xs, ws, c0 * KC, n0, d0);
    }

    // store: rows n0+2p, n0+2p+1
    #pragma unroll
    for (int p = 0; p < 4; p++) {
        float lo[4], hi[4];
        #pragma unroll
        for (int c = 0; c < 4; c++) UNPACK2(lo[c], hi[c], acc[p][c]);
        int r0 = row0 + n0 + 2 * p;
        if (r0 < BN)
            *(float4*)&g_m[r0 * D + d0] = make_float4(lo[0], lo[1], lo[2], lo[3]);
        if (r0 + 1 < BN)
            *(float4*)&g_m[(r0 + 1) * D + d0] = make_float4(hi[0], hi[1], hi[2], hi[3]);
    }
}

// ---------------------------------------------------------------------------
// Kernel 2: edge scatter. One warp per edge, both batches.
//   agg[b, tgt, :] += m[b, src, :] * rel_emb[rel, :]
// ---------------------------------------------------------------------------
__device__ __forceinline__ void red_add_v4(float* addr, float4 v) {
    asm volatile("red.global.add.v4.f32 [%0], {%1, %2, %3, %4};"
                 :: "l"(addr), "f"(v.x), "f"(v.y), "f"(v.z), "f"(v.w)
                 : "memory");
}

__global__ __launch_bounds__(256) void edge_scatter_kernel(
    const float* __restrict__ rel_emb,
    const int* __restrict__ src, const int* __restrict__ tgt,
    const int* __restrict__ rel, int E, int N)
{
    int w = (blockIdx.x * blockDim.x + threadIdx.x) >> 5;
    int lane = threadIdx.x & 31;
    if (w >= E) return;

    int s = __ldg(&src[w]);
    int t = __ldg(&tgt[w]);
    int r = __ldg(&rel[w]);

    float4 rv = *(const float4*)&rel_emb[r * D + lane * 4];

    #pragma unroll
    for (int b = 0; b < BATCH; b++) {
        const float4 mv = *(const float4*)&g_m[(b * N + s) * D + lane * 4];
        float4 p;
        p.x = mv.x * rv.x; p.y = mv.y * rv.y;
        p.z = mv.z * rv.z; p.w = mv.w * rv.w;
        red_add_v4(&g_agg[(b * N + t) * D + lane * 4], p);
    }
}

// ---------------------------------------------------------------------------
// Kernel 3: fused update GEMM (K=256: h then agg) + relu + residual + LN
// ---------------------------------------------------------------------------
__global__ __launch_bounds__(256, 3) void gemm_upd_kernel(
    const float* __restrict__ h,
    const float* __restrict__ b_upd, const float* __restrict__ ln_s,
    const float* __restrict__ ln_b, float* __restrict__ out, int BN)
{
    extern __shared__ float sm[];
    float* xs = sm;                    // 128 x 68
    float* ws = sm + 128 * XS_STRIDE;  // KC x 132

    int tid = threadIdx.x;
    int row0 = blockIdx.x * 64;
    int lane = tid & 31, w = tid >> 5;
    int d0 = lane * 4, n0 = w * 8;

    unsigned long long acc[4][4];
    #pragma unroll
    for (int p = 0; p < 4; p++)
        #pragma unroll
        for (int c = 0; c < 4; c++) acc[p][c] = 0ull;

    #pragma unroll 1
    for (int phase = 0; phase < 2; phase++) {
        const float* X = phase ? (const float*)g_agg : h;
        __syncthreads();               // prior phase's xs reads complete
        load_xtile(xs, X, row0, BN, tid);
        #pragma unroll 1
        for (int c0 = 0; c0 < D / KC; c0++) {
            __syncthreads();
            load_wchunk(ws, g_WuT + (phase * D + c0 * KC) * D, tid);
            __syncthreads();
            mma_chunk(acc, xs, ws, c0 * KC, n0, d0);
        }
    }

    // Epilogue: unpack, bias, relu, residual, LN (warp owns full rows)
    float v[8][4];
    #pragma unroll
    for (int p = 0; p < 4; p++)
        #pragma unroll
        for (int c = 0; c < 4; c++)
            UNPACK2(v[2 * p][c], v[2 * p + 1][c], acc[p][c]);

    float4 bu  = *(const float4*)&b_upd[d0];
    float4 s4  = *(const float4*)&ln_s[d0];
    float4 bb4 = *(const float4*)&ln_b[d0];

    #pragma unroll
    for (int j = 0; j < 8; j++) {
        int row = row0 + n0 + j;           // uniform across warp
        if (row >= BN) continue;
        float4 hr = *(const float4*)&h[row * D + d0];
        float4 t;
        t.x = fmaxf(v[j][0] + bu.x, 0.f) + hr.x;
        t.y = fmaxf(v[j][1] + bu.y, 0.f) + hr.y;
        t.z = fmaxf(v[j][2] + bu.z, 0.f) + hr.z;
        t.w = fmaxf(v[j][3] + bu.w, 0.f) + hr.w;

        float sum = t.x + t.y + t.z + t.w;
        float ssq = t.x * t.x + t.y * t.y + t.z * t.z + t.w * t.w;
        #pragma unroll
        for (int o = 16; o > 0; o >>= 1) {
            sum += __shfl_xor_sync(0xFFFFFFFFu, sum, o);
            ssq += __shfl_xor_sync(0xFFFFFFFFu, ssq, o);
        }
        float mean = sum * (1.f / (float)D);
        float var  = ssq * (1.f / (float)D) - mean * mean;
        float rstd = rsqrtf(var + LN_EPS);

        float4 o4;
        o4.x = (t.x - mean) * rstd * s4.x + bb4.x;
        o4.y = (t.y - mean) * rstd * s4.y + bb4.y;
        o4.z = (t.z - mean) * rstd * s4.z + bb4.z;
        o4.w = (t.w - mean) * rstd * s4.w + bb4.w;
        *(float4*)&out[row * D + d0] = o4;
    }
}

// ---------------------------------------------------------------------------
// Launcher
//  0 h [B*N*D] f32, 1 W_msg [D*D], 2 rel_emb [R*D], 3 W_upd [D*2D],
//  4 b_upd [D], 5 ln_scale [D], 6 ln_bias [D],
//  7 edge_src [E] i32, 8 edge_tgt [E] i32, 9 edge_rel [E] i32, 10 nE scalar
// ---------------------------------------------------------------------------
extern "C" void kernel_launch(void* const* d_in, const int* in_sizes, int n_in,
                              void* d_out, int out_size)
{
    const float* h       = (const float*)d_in[0];
    const float* W_msg   = (const float*)d_in[1];
    const float* rel_emb = (const float*)d_in[2];
    const float* W_upd   = (const float*)d_in[3];
    const float* b_upd   = (const float*)d_in[4];
    const float* ln_s    = (const float*)d_in[5];
    const float* ln_b    = (const float*)d_in[6];
    const int*   e_src   = (const int*)d_in[7];
    const int*   e_tgt   = (const int*)d_in[8];
    const int*   e_rel   = (const int*)d_in[9];
    float* out = (float*)d_out;

    int BN = in_sizes[0] / D;      // B*N = 100000
    int N  = BN / BATCH;           // 50000
    int E  = in_sizes[7];          // 800000

    (void)cudaFuncSetAttribute(gemm_msg_kernel,
        cudaFuncAttributeMaxDynamicSharedMemorySize, (int)(SMEM_GEMM));
    (void)cudaFuncSetAttribute(gemm_upd_kernel,
        cudaFuncAttributeMaxDynamicSharedMemorySize, (int)(SMEM_GEMM));

    // T) transpose weights (reads coalesced; 32768 threads cover both)
    transpose_w_kernel<<<128, 256>>>(W_msg, W_upd);
    // 0) zero agg
    zero_agg_kernel<<<592, 256>>>(BN * D / 4);
    // 1) m = h @ W_msg^T
    gemm_msg_kernel<<<(BN + 63) / 64, 256, SMEM_GEMM>>>(h, BN);
    // 2) edge scatter (one warp per edge)
    edge_scatter_kernel<<<(E + 7) / 8, 256>>>(rel_emb, e_src, e_tgt, e_rel, E, N);
    // 3) fused update + LN
    gemm_upd_kernel<<<(BN + 63) / 64, 256, SMEM_GEMM>>>(h, b_upd, ln_s, ln_b, out, BN);
}

// round 5
// speedup vs baseline: 1.6708x; 1.1931x over previous
#include <cuda_runtime.h>
#include <cuda_bf16.h>

// Problem constants (dataset-fixed)
#define D 128
#define BATCH 2
#define MAXN 50000
#define MAXBN (BATCH * MAXN)
#define MAXE 800000
#define LN_EPS 1e-5f

// Scratch buffers (16B-aligned: float4 / ulonglong2 access)
__device__ __align__(16) float g_m[MAXBN * D];    // h @ W_msg^T
__device__ __align__(16) float g_agg[MAXBN * D];  // gathered aggregate
__device__ __align__(16) float g_WmT[D * D];      // W_msg transposed [k][f]
__device__ __align__(16) float g_WuT[2 * D * D];  // W_upd transposed [k][d]

// CSR-by-target scratch
__device__ int g_cnt[MAXN];        // per-target degree
__device__ int g_excl[MAXN];       // within-block exclusive scan
__device__ int g_blksum[256];      // per-block totals
__device__ int g_blkoff[256];      // scanned block totals
__device__ int g_rowptr[MAXN + 1];
__device__ int g_cursor[MAXN];
__device__ int g_perm[MAXE];

#define SCAN_BLK 256

// ---- packed fp32x2 helpers (sm_100+) --------------------------------------
#define FMA2(d, a, b) \
    asm("fma.rn.f32x2 %0, %1, %2, %0;" : "+l"(d) : "l"(a), "l"(b))
#define SPLAT2(out, f) \
    asm("mov.b64 %0, {%1, %1};" : "=l"(out) : "r"(__float_as_uint(f)))
#define UNPACK2(lo, hi, v) \
    asm("mov.b64 {%0, %1}, %2;" : "=f"(lo), "=f"(hi) : "l"(v))

// smem geometry for GEMMs
#define XS_STRIDE 68
#define WS_STRIDE 132
#define KC 32
#define SMEM_GEMM ((128 * XS_STRIDE + KC * WS_STRIDE) * sizeof(float))

// ---------------------------------------------------------------------------
// Kernel T: transpose weights + zero the histogram counters
// ---------------------------------------------------------------------------
__global__ void transpose_w_kernel(const float* __restrict__ Wm,
                                   const float* __restrict__ Wu, int N) {
    int i = blockIdx.x * blockDim.x + threadIdx.x;   // 32768 threads
    if (i < D * D) {                                  // Wm: [f][k] -> [k][f]
        int f = i >> 7, k = i & 127;
        g_WmT[k * D + f] = Wm[i];
    }
    if (i < 2 * D * D) {                              // Wu: [d][2D] -> [k][d]
        int d = i >> 8, k = i & 255;
        g_WuT[k * D + d] = Wu[i];
    }
    for (int j = i; j < N; j += gridDim.x * blockDim.x) g_cnt[j] = 0;
    if (i < 256) g_blksum[i] = 0;
}

// ---------------------------------------------------------------------------
// CSR build: histogram -> 2-level exclusive scan -> permutation scatter
// ---------------------------------------------------------------------------
__global__ void hist_kernel(const int* __restrict__ tgt, int E) {
    int i = blockIdx.x * blockDim.x + threadIdx.x;
    if (i < E) atomicAdd(&g_cnt[tgt[i]], 1);
}

__global__ void scan1_kernel(int N) {   // per-block exclusive scan of g_cnt
    __shared__ int s[SCAN_BLK];
    int t = threadIdx.x;
    int i = blockIdx.x * SCAN_BLK + t;
    int v = (i < N) ? g_cnt[i] : 0;
    s[t] = v; __syncthreads();
    #pragma unroll
    for (int off = 1; off < SCAN_BLK; off <<= 1) {
        int x = (t >= off) ? s[t - off] : 0;
        __syncthreads();
        s[t] += x; __syncthreads();
    }
    if (i < N) g_excl[i] = s[t] - v;
    if (t == SCAN_BLK - 1) g_blksum[blockIdx.x] = s[t];
}

__global__ void scan2_kernel(int nb) {  // single-block scan of block sums
    __shared__ int s[SCAN_BLK];
    int t = threadIdx.x;
    int v = (t < nb) ? g_blksum[t] : 0;
    s[t] = v; __syncthreads();
    #pragma unroll
    for (int off = 1; off < SCAN_BLK; off <<= 1) {
        int x = (t >= off) ? s[t - off] : 0;
        __syncthreads();
        s[t] += x; __syncthreads();
    }
    if (t < nb) g_blkoff[t] = s[t] - v;
}

__global__ void scan3_kernel(int N, int E) {  // row_ptr = excl + blkoff
    int i = blockIdx.x * blockDim.x + threadIdx.x;
    if (i < N) {
        int rp = g_excl[i] + g_blkoff[i / SCAN_BLK];
        g_rowptr[i] = rp;
        g_cursor[i] = rp;
    }
    if (i == 0) g_rowptr[N] = E;
}

__global__ void scatter_perm_kernel(const int* __restrict__ tgt, int E) {
    int i = blockIdx.x * blockDim.x + threadIdx.x;
    if (i < E) {
        int pos = atomicAdd(&g_cursor[tgt[i]], 1);
        g_perm[pos] = i;
    }
}

// ---------------------------------------------------------------------------
// Gather kernel: one warp per target node, both batches, no atomics.
//   agg[b, n, :] = sum_{e: tgt(e)=n} m[b, src(e), :] * rel_emb[rel(e), :]
// ---------------------------------------------------------------------------
__global__ __launch_bounds__(256) void gather_kernel(
    const float* __restrict__ rel_emb,
    const int* __restrict__ src, const int* __restrict__ rel,
    int N)
{
    int w = blockIdx.x * 8 + (threadIdx.x >> 5);   // node id
    int lane = threadIdx.x & 31;
    if (w >= N) return;

    int beg = g_rowptr[w];
    int end = g_rowptr[w + 1];

    float4 a0 = make_float4(0.f, 0.f, 0.f, 0.f);
    float4 a1 = make_float4(0.f, 0.f, 0.f, 0.f);

    for (int chunk = beg; chunk < end; chunk += 32) {
        int myE = chunk + lane;
        int ms = 0, mr = 0;
        if (myE < end) {
            int id = g_perm[myE];
            ms = __ldg(&src[id]);
            mr = __ldg(&rel[id]);
        }
        int cnt = min(32, end - chunk);
        #pragma unroll 4
        for (int j = 0; j < cnt; j++) {
            int s = __shfl_sync(0xFFFFFFFFu, ms, j);
            int r = __shfl_sync(0xFFFFFFFFu, mr, j);
            float4 rv = *(const float4*)&rel_emb[r * D + lane * 4];
            float4 m0 = *(const float4*)&g_m[s * D + lane * 4];
            float4 m1 = *(const float4*)&g_m[(N + s) * D + lane * 4];
            a0.x += m0.x * rv.x; a0.y += m0.y * rv.y;
            a0.z += m0.z * rv.z; a0.w += m0.w * rv.w;
            a1.x += m1.x * rv.x; a1.y += m1.y * rv.y;
            a1.z += m1.z * rv.z; a1.w += m1.w * rv.w;
        }
    }

    *(float4*)&g_agg[w * D + lane * 4] = a0;
    *(float4*)&g_agg[(N + w) * D + lane * 4] = a1;
}

// ---------------------------------------------------------------------------
// GEMM helpers (unchanged from round 4)
// ---------------------------------------------------------------------------
__device__ __forceinline__ void load_xtile(float* xs, const float* __restrict__ X,
                                           int row0, int BN, int tid) {
    #pragma unroll 2
    for (int i = tid; i < 64 * 32; i += 256) {
        int n = i >> 5, k4 = i & 31;
        int row = row0 + n;
        float4 v = make_float4(0.f, 0.f, 0.f, 0.f);
        if (row < BN) v = *(const float4*)&X[row * D + k4 * 4];
        xs[(k4 * 4 + 0) * XS_STRIDE + n] = v.x;
        xs[(k4 * 4 + 1) * XS_STRIDE + n] = v.y;
        xs[(k4 * 4 + 2) * XS_STRIDE + n] = v.z;
        xs[(k4 * 4 + 3) * XS_STRIDE + n] = v.w;
    }
}

__device__ __forceinline__ void load_wchunk(float* ws, const float* __restrict__ Wt,
                                            int tid) {
    #pragma unroll 2
    for (int i = tid; i < KC * 32; i += 256) {
        int kk = i >> 5, d4 = i & 31;
        float4 v = *(const float4*)&Wt[kk * D + d4 * 4];
        *(float4*)&ws[kk * WS_STRIDE + d4 * 4] = v;
    }
}

__device__ __forceinline__ void mma_chunk(unsigned long long acc[4][4],
                                          const float* xs, const float* ws,
                                          int kbase, int n0, int d0) {
    #pragma unroll 4
    for (int kk = 0; kk < KC; kk++) {
        float4 b4 = *(const float4*)&ws[kk * WS_STRIDE + d0];
        unsigned long long bp0, bp1, bp2, bp3;
        SPLAT2(bp0, b4.x); SPLAT2(bp1, b4.y);
        SPLAT2(bp2, b4.z); SPLAT2(bp3, b4.w);
        const ulonglong2* ap =
            (const ulonglong2*)&xs[(kbase + kk) * XS_STRIDE + n0];
        ulonglong2 A0 = ap[0];
        ulonglong2 A1 = ap[1];
        FMA2(acc[0][0], A0.x, bp0); FMA2(acc[0][1], A0.x, bp1);
        FMA2(acc[0][2], A0.x, bp2); FMA2(acc[0][3], A0.x, bp3);
        FMA2(acc[1][0], A0.y, bp0); FMA2(acc[1][1], A0.y, bp1);
        FMA2(acc[1][2], A0.y, bp2); FMA2(acc[1][3], A0.y, bp3);
        FMA2(acc[2][0], A1.x, bp0); FMA2(acc[2][1], A1.x, bp1);
        FMA2(acc[2][2], A1.x, bp2); FMA2(acc[2][3], A1.x, bp3);
        FMA2(acc[3][0], A1.y, bp0); FMA2(acc[3][1], A1.y, bp1);
        FMA2(acc[3][2], A1.y, bp2); FMA2(acc[3][3], A1.y, bp3);
    }
}

// ---------------------------------------------------------------------------
// Kernel 1: m = h @ W_msg^T
// ---------------------------------------------------------------------------
__global__ __launch_bounds__(256, 3) void gemm_msg_kernel(
    const float* __restrict__ h, int BN)
{
    extern __shared__ float sm[];
    float* xs = sm;
    float* ws = sm + 128 * XS_STRIDE;

    int tid = threadIdx.x;
    int row0 = blockIdx.x * 64;
    int lane = tid & 31, w = tid >> 5;
    int d0 = lane * 4, n0 = w * 8;

    unsigned long long acc[4][4];
    #pragma unroll
    for (int p = 0; p < 4; p++)
        #pragma unroll
        for (int c = 0; c < 4; c++) acc[p][c] = 0ull;

    load_xtile(xs, h, row0, BN, tid);

    #pragma unroll 1
    for (int c0 = 0; c0 < D / KC; c0++) {
        __syncthreads();
        load_wchunk(ws, g_WmT + c0 * KC * D, tid);
        __syncthreads();
        mma_chunk(acc, xs, ws, c0 * KC, n0, d0);
    }

    #pragma unroll
    for (int p = 0; p < 4; p++) {
        float lo[4], hi[4];
        #pragma unroll
        for (int c = 0; c < 4; c++) UNPACK2(lo[c], hi[c], acc[p][c]);
        int r0 = row0 + n0 + 2 * p;
        if (r0 < BN)
            *(float4*)&g_m[r0 * D + d0] = make_float4(lo[0], lo[1], lo[2], lo[3]);
        if (r0 + 1 < BN)
            *(float4*)&g_m[(r0 + 1) * D + d0] = make_float4(hi[0], hi[1], hi[2], hi[3]);
    }
}

// ---------------------------------------------------------------------------
// Kernel 3: fused update GEMM (K=256: h then agg) + relu + residual + LN
// ---------------------------------------------------------------------------
__global__ __launch_bounds__(256, 3) void gemm_upd_kernel(
    const float* __restrict__ h,
    const float* __restrict__ b_upd, const float* __restrict__ ln_s,
    const float* __restrict__ ln_b, float* __restrict__ out, int BN)
{
    extern __shared__ float sm[];
    float* xs = sm;
    float* ws = sm + 128 * XS_STRIDE;

    int tid = threadIdx.x;
    int row0 = blockIdx.x * 64;
    int lane = tid & 31, w = tid >> 5;
    int d0 = lane * 4, n0 = w * 8;

    unsigned long long acc[4][4];
    #pragma unroll
    for (int p = 0; p < 4; p++)
        #pragma unroll
        for (int c = 0; c < 4; c++) acc[p][c] = 0ull;

    #pragma unroll 1
    for (int phase = 0; phase < 2; phase++) {
        const float* X = phase ? (const float*)g_agg : h;
        __syncthreads();
        load_xtile(xs, X, row0, BN, tid);
        #pragma unroll 1
        for (int c0 = 0; c0 < D / KC; c0++) {
            __syncthreads();
            load_wchunk(ws, g_WuT + (phase * D + c0 * KC) * D, tid);
            __syncthreads();
            mma_chunk(acc, xs, ws, c0 * KC, n0, d0);
        }
    }

    float v[8][4];
    #pragma unroll
    for (int p = 0; p < 4; p++)
        #pragma unroll
        for (int c = 0; c < 4; c++)
            UNPACK2(v[2 * p][c], v[2 * p + 1][c], acc[p][c]);

    float4 bu  = *(const float4*)&b_upd[d0];
    float4 s4  = *(const float4*)&ln_s[d0];
    float4 bb4 = *(const float4*)&ln_b[d0];

    #pragma unroll
    for (int j = 0; j < 8; j++) {
        int row = row0 + n0 + j;
        if (row >= BN) continue;
        float4 hr = *(const float4*)&h[row * D + d0];
        float4 t;
        t.x = fmaxf(v[j][0] + bu.x, 0.f) + hr.x;
        t.y = fmaxf(v[j][1] + bu.y, 0.f) + hr.y;
        t.z = fmaxf(v[j][2] + bu.z, 0.f) + hr.z;
        t.w = fmaxf(v[j][3] + bu.w, 0.f) + hr.w;

        float sum = t.x + t.y + t.z + t.w;
        float ssq = t.x * t.x + t.y * t.y + t.z * t.z + t.w * t.w;
        #pragma unroll
        for (int o = 16; o > 0; o >>= 1) {
            sum += __shfl_xor_sync(0xFFFFFFFFu, sum, o);
            ssq += __shfl_xor_sync(0xFFFFFFFFu, ssq, o);
        }
        float mean = sum * (1.f / (float)D);
        float var  = ssq * (1.f / (float)D) - mean * mean;
        float rstd = rsqrtf(var + LN_EPS);

        float4 o4;
        o4.x = (t.x - mean) * rstd * s4.x + bb4.x;
        o4.y = (t.y - mean) * rstd * s4.y + bb4.y;
        o4.z = (t.z - mean) * rstd * s4.z + bb4.z;
        o4.w = (t.w - mean) * rstd * s4.w + bb4.w;
        *(float4*)&out[row * D + d0] = o4;
    }
}

// ---------------------------------------------------------------------------
// Launcher
//  0 h [B*N*D] f32, 1 W_msg [D*D], 2 rel_emb [R*D], 3 W_upd [D*2D],
//  4 b_upd [D], 5 ln_scale [D], 6 ln_bias [D],
//  7 edge_src [E] i32, 8 edge_tgt [E] i32, 9 edge_rel [E] i32, 10 nE scalar
// ---------------------------------------------------------------------------
extern "C" void kernel_launch(void* const* d_in, const int* in_sizes, int n_in,
                              void* d_out, int out_size)
{
    const float* h       = (const float*)d_in[0];
    const float* W_msg   = (const float*)d_in[1];
    const float* rel_emb = (const float*)d_in[2];
    const float* W_upd   = (const float*)d_in[3];
    const float* b_upd   = (const float*)d_in[4];
    const float* ln_s    = (const float*)d_in[5];
    const float* ln_b    = (const float*)d_in[6];
    const int*   e_src   = (const int*)d_in[7];
    const int*   e_tgt   = (const int*)d_in[8];
    const int*   e_rel   = (const int*)d_in[9];
    float* out = (float*)d_out;

    int BN = in_sizes[0] / D;      // B*N = 100000
    int N  = BN / BATCH;           // 50000
    int E  = in_sizes[7];          // 800000

    (void)cudaFuncSetAttribute(gemm_msg_kernel,
        cudaFuncAttributeMaxDynamicSharedMemorySize, (int)(SMEM_GEMM));
    (void)cudaFuncSetAttribute(gemm_upd_kernel,
        cudaFuncAttributeMaxDynamicSharedMemorySize, (int)(SMEM_GEMM));

    int nb = (N + SCAN_BLK - 1) / SCAN_BLK;   // 196 <= 256

    // T) transpose weights + zero histogram
    transpose_w_kernel<<<128, 256>>>(W_msg, W_upd, N);
    // CSR build
    hist_kernel<<<(E + 255) / 256, 256>>>(e_tgt, E);
    scan1_kernel<<<nb, SCAN_BLK>>>(N);
    scan2_kernel<<<1, SCAN_BLK>>>(nb);
    scan3_kernel<<<(N + 255) / 256, 256>>>(N, E);
    scatter_perm_kernel<<<(E + 255) / 256, 256>>>(e_tgt, E);
    // 1) m = h @ W_msg^T
    gemm_msg_kernel<<<(BN + 63) / 64, 256, SMEM_GEMM>>>(h, BN);
    // 2) gather (no atomics)
    gather_kernel<<<(N + 7) / 8, 256>>>(rel_emb, e_src, e_rel, N);
    // 3) fused update + LN
    gemm_upd_kernel<<<(BN + 63) / 64, 256, SMEM_GEMM>>>(h, b_upd, ln_s, ln_b, out, BN);
}

// round 7
// speedup vs baseline: 1.9659x; 1.1766x over previous
#include <cuda_runtime.h>
#include <cstdint>

// Problem constants (dataset-fixed)
#define D 128
#define BATCH 2
#define MAXN 50000
#define MAXBN (BATCH * MAXN)
#define MAXE 800000
#define LN_EPS 1e-5f

// Scratch buffers
__device__ __align__(16) float g_m[MAXBN * D];    // h @ W_msg^T
__device__ __align__(16) float g_agg[MAXBN * D];  // gathered aggregate
__device__ __align__(16) float g_Wm[D * D];       // W_msg, tf32-rounded
__device__ __align__(16) float g_Wu[D * 2 * D];   // W_upd, tf32-rounded

// CSR-by-target scratch
__device__ int g_cnt[MAXN];
__device__ int g_excl[MAXN];
__device__ int g_blksum[256];
__device__ int g_rowptr[MAXN + 1];
__device__ int g_cursor[MAXN];
__device__ int g_perm[MAXE];

#define SCAN_BLK 256

// ---- tf32 round-to-nearest (RNA via bit trick) -----------------------------
__device__ __forceinline__ float tf32_rn(float x) {
    uint32_t b = __float_as_uint(x);
    b = (b + 0x00001000u) & 0xFFFFE000u;
    return __uint_as_float(b);
}

// ---- warp-level TF32 MMA (sm_80+ baseline PTX; maps to HMMA) ---------------
__device__ __forceinline__ void mma_tf32(float c[4],
                                         uint32_t a0, uint32_t a1,
                                         uint32_t a2, uint32_t a3,
                                         uint32_t b0, uint32_t b1) {
    asm volatile(
        "mma.sync.aligned.m16n8k8.row.col.f32.tf32.tf32.f32 "
        "{%0,%1,%2,%3}, {%4,%5,%6,%7}, {%8,%9}, {%0,%1,%2,%3};"
        : "+f"(c[0]), "+f"(c[1]), "+f"(c[2]), "+f"(c[3])
        : "r"(a0), "r"(a1), "r"(a2), "r"(a3), "r"(b0), "r"(b1));
}

// smem geometry: A tile [128m][132k] + B tile [128n][132k] floats
#define TS 132
#define SM_A_OFF 0
#define SM_B_OFF (128 * TS)
#define SMEM_MMA ((2 * 128 * TS) * sizeof(float))   // 135168 B

// ============================================================================
// prep: zero counters + tf32-round weights
// ============================================================================
__global__ void prep_kernel(const float* __restrict__ Wm,
                            const float* __restrict__ Wu, int N) {
    int i = blockIdx.x * blockDim.x + threadIdx.x;  // >= 50176 threads
    if (i < N) g_cnt[i] = 0;
    if (i < 256) g_blksum[i] = 0;
    if (i < D * D) g_Wm[i] = tf32_rn(Wm[i]);
    if (i < 2 * D * D) g_Wu[i] = tf32_rn(Wu[i]);
}

// ============================================================================
// CSR build (histogram -> scan1 -> merged scan23 -> permutation scatter)
// ============================================================================
__global__ void hist_kernel(const int* __restrict__ tgt, int E) {
    int i = blockIdx.x * blockDim.x + threadIdx.x;
    if (i < E) atomicAdd(&g_cnt[tgt[i]], 1);
}

__global__ void scan1_kernel(int N) {
    __shared__ int s[SCAN_BLK];
    int t = threadIdx.x;
    int i = blockIdx.x * SCAN_BLK + t;
    int v = (i < N) ? g_cnt[i] : 0;
    s[t] = v; __syncthreads();
    #pragma unroll
    for (int off = 1; off < SCAN_BLK; off <<= 1) {
        int x = (t >= off) ? s[t - off] : 0;
        __syncthreads();
        s[t] += x; __syncthreads();
    }
    if (i < N) g_excl[i] = s[t] - v;
    if (t == SCAN_BLK - 1) g_blksum[blockIdx.x] = s[t];
}

__global__ void scan23_kernel(int N, int E) {
    __shared__ int s[SCAN_BLK];
    int t = threadIdx.x;
    int b = blockIdx.x;
    s[t] = (t < b) ? g_blksum[t] : 0;
    __syncthreads();
    #pragma unroll
    for (int off = SCAN_BLK / 2; off > 0; off >>= 1) {
        if (t < off) s[t] += s[t + off];
        __syncthreads();
    }
    int offset = s[0];
    int i = b * SCAN_BLK + t;
    if (i < N) {
        int rp = g_excl[i] + offset;
        g_rowptr[i] = rp;
        g_cursor[i] = rp;
    }
    if (b == 0 && t == 0) g_rowptr[N] = E;
}

__global__ void scatter_perm_kernel(const int* __restrict__ tgt, int E) {
    int i = blockIdx.x * blockDim.x + threadIdx.x;
    if (i < E) {
        int pos = atomicAdd(&g_cursor[tgt[i]], 1);
        g_perm[pos] = i;
    }
}

// ============================================================================
// Gather: one warp per target node, both batches, no atomics (round-5 winner)
// ============================================================================
__global__ __launch_bounds__(256) void gather_kernel(
    const float* __restrict__ rel_emb,
    const int* __restrict__ src, const int* __restrict__ rel, int N)
{
    int w = blockIdx.x * 8 + (threadIdx.x >> 5);
    int lane = threadIdx.x & 31;
    if (w >= N) return;

    int beg = g_rowptr[w];
    int end = g_rowptr[w + 1];

    float4 a0 = make_float4(0.f, 0.f, 0.f, 0.f);
    float4 a1 = make_float4(0.f, 0.f, 0.f, 0.f);

    for (int chunk = beg; chunk < end; chunk += 32) {
        int myE = chunk + lane;
        int ms = 0, mr = 0;
        if (myE < end) {
            int id = g_perm[myE];
            ms = __ldg(&src[id]);
            mr = __ldg(&rel[id]);
        }
        int cnt = min(32, end - chunk);
        #pragma unroll 4
        for (int j = 0; j < cnt; j++) {
            int s = __shfl_sync(0xFFFFFFFFu, ms, j);
            int r = __shfl_sync(0xFFFFFFFFu, mr, j);
            float4 rv = *(const float4*)&rel_emb[r * D + lane * 4];
            float4 m0 = *(const float4*)&g_m[s * D + lane * 4];
            float4 m1 = *(const float4*)&g_m[(N + s) * D + lane * 4];
            a0.x += m0.x * rv.x; a0.y += m0.y * rv.y;
            a0.z += m0.z * rv.z; a0.w += m0.w * rv.w;
            a1.x += m1.x * rv.x; a1.y += m1.y * rv.y;
            a1.z += m1.z * rv.z; a1.w += m1.w * rv.w;
        }
    }

    *(float4*)&g_agg[w * D + lane * 4] = a0;
    *(float4*)&g_agg[(N + w) * D + lane * 4] = a1;
}

// ============================================================================
// Tile loaders
// ============================================================================
// A: rows row0..row0+127 of X (row-major, ldx floats), tf32-rounded
__device__ __forceinline__ void load_a_tile(float* As, const float* __restrict__ X,
                                            int ldx, int row0, int limit, int tid) {
    #pragma unroll 4
    for (int it = tid; it < 4096; it += 256) {       // 128 rows x 32 float4
        int m = it >> 5;
        int k = (it & 31) * 4;
        int row = row0 + m;
        float4 v = make_float4(0.f, 0.f, 0.f, 0.f);
        if (row < limit) v = *(const float4*)&X[(long)row * ldx + k];
        v.x = tf32_rn(v.x); v.y = tf32_rn(v.y);
        v.z = tf32_rn(v.z); v.w = tf32_rn(v.w);
        *(float4*)&As[m * TS + k] = v;
    }
}

// B: 128 output rows of pre-rounded W (row-major, ldw floats, k-offset koff)
__device__ __forceinline__ void load_b_tile(float* Bs, const float* __restrict__ W,
                                            int ldw, int koff, int tid) {
    #pragma unroll 4
    for (int it = tid; it < 4096; it += 256) {
        int n = it >> 5;
        int k = (it & 31) * 4;
        float4 v = *(const float4*)&W[(long)n * ldw + koff + k];
        *(float4*)&Bs[n * TS + k] = v;
    }
}

// 16 k-steps of m16n8k8 over the resident tile. Each warp: rows m0..m0+15.
__device__ __forceinline__ void mma_tile(float c[16][4], const uint32_t* As,
                                         const uint32_t* Bs, int m0,
                                         int gid, int tg) {
    #pragma unroll 1
    for (int ks = 0; ks < 16; ks++) {
        int kb = ks * 8;
        uint32_t a0 = As[(m0 + gid) * TS + kb + tg];
        uint32_t a1 = As[(m0 + gid + 8) * TS + kb + tg];
        uint32_t a2 = As[(m0 + gid) * TS + kb + tg + 4];
        uint32_t a3 = As[(m0 + gid + 8) * TS + kb + tg + 4];
        #pragma unroll
        for (int t = 0; t < 16; t++) {
            uint32_t b0 = Bs[(t * 8 + gid) * TS + kb + tg];
            uint32_t b1 = Bs[(t * 8 + gid) * TS + kb + tg + 4];
            mma_tf32(c[t], a0, a1, a2, a3, b0, b1);
        }
    }
}

// ============================================================================
// GEMM 1: g_m = h @ W_msg^T   (tile 128x128, K=128)
// ============================================================================
__global__ __launch_bounds__(256) void gemm_msg_mma(
    const float* __restrict__ h, int BN)
{
    extern __shared__ float sm[];
    float* As = sm + SM_A_OFF;
    float* Bs = sm + SM_B_OFF;

    int tid = threadIdx.x;
    int lane = tid & 31, warp = tid >> 5;
    int gid = lane >> 2, tg = lane & 3;
    int m0 = warp * 16;
    int row0 = blockIdx.x * 128;

    float c[16][4];
    #pragma unroll
    for (int t = 0; t < 16; t++)
        #pragma unroll
        for (int q = 0; q < 4; q++) c[t][q] = 0.f;

    load_a_tile(As, h, D, row0, BN, tid);
    load_b_tile(Bs, g_Wm, D, 0, tid);
    __syncthreads();

    mma_tile(c, (const uint32_t*)As, (const uint32_t*)Bs, m0, gid, tg);

    // store fragments directly (float2 per row per tile)
    int r0 = row0 + m0 + gid;
    int r1 = r0 + 8;
    #pragma unroll
    for (int t = 0; t < 16; t++) {
        int col = t * 8 + tg * 2;
        if (r0 < BN) *(float2*)&g_m[(long)r0 * D + col] = make_float2(c[t][0], c[t][1]);
        if (r1 < BN) *(float2*)&g_m[(long)r1 * D + col] = make_float2(c[t][2], c[t][3]);
    }
}

// ============================================================================
// GEMM 2: out = LN(h + relu([h|agg] @ W_upd^T + b))   (K=256, 2 phases)
// ============================================================================
__global__ __launch_bounds__(256) void gemm_upd_mma(
    const float* __restrict__ h,
    const float* __restrict__ b_upd, const float* __restrict__ ln_s,
    const float* __restrict__ ln_b, float* __restrict__ out, int BN)
{
    extern __shared__ float sm[];
    float* As = sm + SM_A_OFF;
    float* Bs = sm + SM_B_OFF;

    int tid = threadIdx.x;
    int lane = tid & 31, warp = tid >> 5;
    int gid = lane >> 2, tg = lane & 3;
    int m0 = warp * 16;
    int row0 = blockIdx.x * 128;

    float c[16][4];
    #pragma unroll
    for (int t = 0; t < 16; t++)
        #pragma unroll
        for (int q = 0; q < 4; q++) c[t][q] = 0.f;

    #pragma unroll 1
    for (int phase = 0; phase < 2; phase++) {
        const float* X = (phase == 0) ? h : (const float*)g_agg;
        __syncthreads();                    // prior phase reads complete
        load_a_tile(As, X, D, row0, BN, tid);
        load_b_tile(Bs, g_Wu, 2 * D, phase * D, tid);
        __syncthreads();
        mma_tile(c, (const uint32_t*)As, (const uint32_t*)Bs, m0, gid, tg);
    }

    // stage C into As region for per-row epilogue
    __syncthreads();
    #pragma unroll
    for (int t = 0; t < 16; t++) {
        int col = t * 8 + tg * 2;
        *(float2*)&As[(m0 + gid) * TS + col]     = make_float2(c[t][0], c[t][1]);
        *(float2*)&As[(m0 + gid + 8) * TS + col] = make_float2(c[t][2], c[t][3]);
    }
    __syncthreads();

    if (tid < 128) {
        int row = row0 + tid;
        if (row < BN) {
            float* Crow = &As[tid * TS];
            // pass 1: bias + relu + residual, stats; write v back in place
            float sum = 0.f, ssq = 0.f;
            #pragma unroll 4
            for (int n = 0; n < D; n += 4) {
                float4 cv = *(float4*)&Crow[n];
                float4 bu = __ldg((const float4*)&b_upd[n]);
                float4 hr = *(const float4*)&h[(long)row * D + n];
                float v0 = fmaxf(cv.x + bu.x, 0.f) + hr.x;
                float v1 = fmaxf(cv.y + bu.y, 0.f) + hr.y;
                float v2 = fmaxf(cv.z + bu.z, 0.f) + hr.z;
                float v3 = fmaxf(cv.w + bu.w, 0.f) + hr.w;
                *(float4*)&Crow[n] = make_float4(v0, v1, v2, v3);
                sum += v0 + v1 + v2 + v3;
                ssq += v0 * v0 + v1 * v1 + v2 * v2 + v3 * v3;
            }
            float mean = sum * (1.f / (float)D);
            float var  = ssq * (1.f / (float)D) - mean * mean;
            float rstd = rsqrtf(var + LN_EPS);
            // pass 2: normalize + affine + store
            #pragma unroll 4
            for (int n = 0; n < D; n += 4) {
                float4 v  = *(float4*)&Crow[n];
                float4 s4 = __ldg((const float4*)&ln_s[n]);
                float4 b4 = __ldg((const float4*)&ln_b[n]);
                float4 o;
                o.x = (v.x - mean) * rstd * s4.x + b4.x;
                o.y = (v.y - mean) * rstd * s4.y + b4.y;
                o.z = (v.z - mean) * rstd * s4.z + b4.z;
                o.w = (v.w - mean) * rstd * s4.w + b4.w;
                *(float4*)&out[(long)row * D + n] = o;
            }
        }
    }
}

// ---------------------------------------------------------------------------
// Launcher
//  0 h [B*N*D] f32, 1 W_msg [D*D], 2 rel_emb [R*D], 3 W_upd [D*2D],
//  4 b_upd [D], 5 ln_scale [D], 6 ln_bias [D],
//  7 edge_src [E] i32, 8 edge_tgt [E] i32, 9 edge_rel [E] i32, 10 nE scalar
// ---------------------------------------------------------------------------
extern "C" void kernel_launch(void* const* d_in, const int* in_sizes, int n_in,
                              void* d_out, int out_size)
{
    const float* h       = (const float*)d_in[0];
    const float* W_msg   = (const float*)d_in[1];
    const float* rel_emb = (const float*)d_in[2];
    const float* W_upd   = (const float*)d_in[3];
    const float* b_upd   = (const float*)d_in[4];
    const float* ln_s    = (const float*)d_in[5];
    const float* ln_b    = (const float*)d_in[6];
    const int*   e_src   = (const int*)d_in[7];
    const int*   e_tgt   = (const int*)d_in[8];
    const int*   e_rel   = (const int*)d_in[9];
    float* out = (float*)d_out;

    int BN = in_sizes[0] / D;      // 100000
    int N  = BN / BATCH;           // 50000
    int E  = in_sizes[7];          // 800000

    (void)cudaFuncSetAttribute(gemm_msg_mma,
        cudaFuncAttributeMaxDynamicSharedMemorySize, (int)SMEM_MMA);
    (void)cudaFuncSetAttribute(gemm_upd_mma,
        cudaFuncAttributeMaxDynamicSharedMemorySize, (int)SMEM_MMA);

    int nb = (N + SCAN_BLK - 1) / SCAN_BLK;   // 196
    int tiles = (BN + 127) / 128;             // 782

    prep_kernel<<<(N + 255) / 256, 256>>>(W_msg, W_upd, N);
    hist_kernel<<<(E + 255) / 256, 256>>>(e_tgt, E);
    scan1_kernel<<<nb, SCAN_BLK>>>(N);
    scan23_kernel<<<nb, SCAN_BLK>>>(N, E);
    scatter_perm_kernel<<<(E + 255) / 256, 256>>>(e_tgt, E);
    gemm_msg_mma<<<tiles, 256, SMEM_MMA>>>(h, BN);
    gather_kernel<<<(N + 7) / 8, 256>>>(rel_emb, e_src, e_rel, N);
    gemm_upd_mma<<<tiles, 256, SMEM_MMA>>>(h, b_upd, ln_s, ln_b, out, BN);
}